// round 11
// baseline (speedup 1.0000x reference)
#include <cuda_runtime.h>
#include <cuda_bf16.h>
#include <mma.h>
#include <cstdint>

using namespace nvcuda;

#define BB 64
#define TT 4096
#define DD 128
#define HH 128
#define GG 384            // 3*H, gates [r, z, n]

#define NC 16             // chunks
#define CC 256            // timesteps per chunk

typedef unsigned long long u64;
typedef unsigned int u32;

// ---------------- scratch (device globals; no allocation) -------------------
__device__ float g_gi0[(size_t)TT * BB * GG];   // raw gi (NO b_ih; rec adds it)
__device__ float g_gi1[(size_t)TT * BB * GG];
__device__ float g_h0 [(size_t)TT * BB * HH];
__device__ float g_hst1[BB * HH];
// bf16 hi/lo activation images, plain row-major per t: [t][b][k], 8192 elems/t
__device__ __nv_bfloat16 g_axh[(size_t)TT * 8192];
__device__ __nv_bfloat16 g_axl[(size_t)TT * 8192];
__device__ __nv_bfloat16 g_ahh[(size_t)TT * 8192];
__device__ __nv_bfloat16 g_ahl[(size_t)TT * 8192];
// bf16 hi/lo W images, row-major [384][128] per layer
__device__ __nv_bfloat16 g_wh[2][384 * 128];
__device__ __nv_bfloat16 g_wl[2][384 * 128];

// ---------------- helpers ---------------------------------------------------
__device__ __forceinline__ u64 fma2p(u64 d, u64 a, u64 b) {
    asm("fma.rn.f32x2 %0, %1, %2, %0;" : "+l"(d) : "l"(a), "l"(b)); return d;
}
__device__ __forceinline__ float fsig(float x) {
    return __fdividef(1.0f, 1.0f + __expf(-x));
}
__device__ __forceinline__ float ftanh(float x) {
    return 1.0f - __fdividef(2.0f, __expf(2.0f * x) + 1.0f);
}
__device__ __forceinline__ void split_pack(float x0, float x1, u32& hi, u32& lo) {
    __nv_bfloat16 h0 = __float2bfloat16(x0);
    __nv_bfloat16 h1 = __float2bfloat16(x1);
    __nv_bfloat16 l0 = __float2bfloat16(x0 - __bfloat162float(h0));
    __nv_bfloat16 l1 = __float2bfloat16(x1 - __bfloat162float(h1));
    hi = (u32)__bfloat16_as_ushort(h0) | ((u32)__bfloat16_as_ushort(h1) << 16);
    lo = (u32)__bfloat16_as_ushort(l0) | ((u32)__bfloat16_as_ushort(l1) << 16);
}

// ---------------- conversion kernels ---------------------------------------
__global__ void conv_w(const float* __restrict__ W0, const float* __restrict__ W1) {
    int i = blockIdx.x * blockDim.x + threadIdx.x;
    if (i >= 2 * 384 * 64) return;
    const int L = i / (384 * 64);
    const int rem = i % (384 * 64);
    const int j = rem >> 6;
    const int p = rem & 63;
    const float* W = L ? W1 : W0;
    u32 hi, lo;
    split_pack(W[(size_t)j * 128 + 2 * p], W[(size_t)j * 128 + 2 * p + 1], hi, lo);
    *(u32*)&g_wh[L][j * 128 + 2 * p] = hi;
    *(u32*)&g_wl[L][j * 128 + 2 * p] = lo;
}

__global__ void conv_x(const float* __restrict__ X) {
    int i = blockIdx.x * blockDim.x + threadIdx.x;
    const int p = i & 63;
    const int b = (i >> 6) & 63;
    const int t = i >> 12;
    if (t >= TT) return;
    const float* src = X + ((size_t)b * TT + t) * DD + 2 * p;
    u32 hi, lo;
    split_pack(src[0], src[1], hi, lo);
    *(u32*)&g_axh[(size_t)t * 8192 + b * 128 + 2 * p] = hi;
    *(u32*)&g_axl[(size_t)t * 8192 + b * 128 + 2 * p] = lo;
}

__global__ void conv_h(int c) {
    int i = blockIdx.x * blockDim.x + threadIdx.x;
    const int p = i & 63;
    const int b = (i >> 6) & 63;
    const int tl = i >> 12;
    if (tl >= CC) return;
    const int t = c * CC + tl;
    const float* src = g_h0 + ((size_t)t * BB + b) * HH + 2 * p;
    u32 hi, lo;
    split_pack(src[0], src[1], hi, lo);
    *(u32*)&g_ahh[(size_t)t * 8192 + b * 128 + 2 * p] = hi;
    *(u32*)&g_ahl[(size_t)t * 8192 + b * 128 + 2 * p] = lo;
}

// ---------------- WMMA GEMM chunk -------------------------------------------
// D[384 j, 64 b] = W[384,128] @ act[64,128]^T per t, 3-term bf16 split, fp32 acc.
// 8 warps; warp w owns m-tiles 3w..3w+2; 4 n-tiles (16 batches each);
// act hi/lo staged in smem; W fragments from global (L1/L2-resident).
__global__ void __launch_bounds__(256, 1) gemm_wmma(
    const __nv_bfloat16* __restrict__ ah, const __nv_bfloat16* __restrict__ al,
    const __nv_bfloat16* __restrict__ wh, const __nv_bfloat16* __restrict__ wl,
    float* __restrict__ dst, int c, int nstripes)
{
    __shared__ __align__(16) __nv_bfloat16 s_ah[64 * 128];
    __shared__ __align__(16) __nv_bfloat16 s_al[64 * 128];
    const int tid = threadIdx.x;
    const int warp = tid >> 5;

    for (int t = c * CC + blockIdx.x; t < (c + 1) * CC; t += nstripes) {
        // stage act hi/lo (16 KB each)
        {
            const uint4* sh = (const uint4*)(ah + (size_t)t * 8192);
            const uint4* sl = (const uint4*)(al + (size_t)t * 8192);
            uint4* dh = (uint4*)s_ah;
            uint4* dl = (uint4*)s_al;
            #pragma unroll
            for (int i = tid; i < 1024; i += 256) { dh[i] = sh[i]; dl[i] = sl[i]; }
        }
        __syncthreads();

        #pragma unroll
        for (int mi = 0; mi < 3; mi++) {
            const int j0 = (warp * 3 + mi) * 16;

            wmma::fragment<wmma::accumulator, 16, 16, 16, float> acc[4];
            #pragma unroll
            for (int n = 0; n < 4; n++) wmma::fill_fragment(acc[n], 0.0f);

            #pragma unroll
            for (int pass = 0; pass < 3; pass++) {
                const __nv_bfloat16* W = (pass == 2) ? wl : wh;
                const __nv_bfloat16* B = (pass == 1) ? s_al : s_ah;
                #pragma unroll
                for (int k = 0; k < 8; k++) {
                    wmma::fragment<wmma::matrix_a, 16, 16, 16, __nv_bfloat16, wmma::row_major> af;
                    wmma::load_matrix_sync(af, W + (size_t)j0 * 128 + k * 16, 128);
                    #pragma unroll
                    for (int n = 0; n < 4; n++) {
                        wmma::fragment<wmma::matrix_b, 16, 16, 16, __nv_bfloat16, wmma::col_major> bf;
                        wmma::load_matrix_sync(bf, B + n * 16 * 128 + k * 16, 128);
                        wmma::mma_sync(acc[n], af, bf, acc[n]);
                    }
                }
            }

            float* dp = dst + (size_t)t * BB * GG;
            #pragma unroll
            for (int n = 0; n < 4; n++)
                wmma::store_matrix_sync(dp + (size_t)(n * 16) * GG + j0, acc[n],
                                        GG, wmma::mem_col_major);
        }
        __syncthreads();
    }
}

// ---------------- rec chunk (R9 winner + b_ih fold) --------------------------
__global__ __launch_bounds__(384, 1) void rec_chunk(
    const float* __restrict__ Whh,
    const float* __restrict__ bhh,
    const float* __restrict__ bih,
    int layer, int c,
    float* __restrict__ hout)
{
    const int j = threadIdx.x;
    const int e = j & 127;
    const bool isGate = (j < 128);
    const int b = blockIdx.x;

    u64 w[64];
    {
        const ulonglong2* wr = (const ulonglong2*)(Whh + (size_t)j * 128);
        #pragma unroll
        for (int k = 0; k < 32; k++) { ulonglong2 v = wr[k]; w[2*k] = v.x; w[2*k+1] = v.y; }
    }
    const float bj = bhh[j];
    const float biOwn = (j < 256) ? bih[j] : 0.0f;
    const float biN   = isGate ? bih[256 + e] : 0.0f;

    const float* gi = layer ? g_gi1 : g_gi0;
    const size_t S = (size_t)BB * GG;
    const float* pOwn = gi + (size_t)b * GG + j;
    const float* pN   = gi + (size_t)b * GG + 256 + e;

    __shared__ __align__(16) float s_h[128];
    __shared__ float s_gh[256];

    const int t0 = c * CC, t1 = t0 + CC;

    float hreg = 0.0f;
    if (isGate) {
        if (c == 0) hreg = 0.0f;
        else if (layer == 0) hreg = g_h0[((size_t)(t0 - 1) * BB + b) * HH + e];
        else hreg = g_hst1[b * HH + e];
        s_h[e] = hreg;
    }
    __syncthreads();

    float gOwn = (j < 256) ? (pOwn[(size_t)t0 * S] + biOwn) : 0.0f;
    float gN   = isGate ? (pN[(size_t)t0 * S] + biN) : 0.0f;

    const ulonglong2* h16 = (const ulonglong2*)s_h;

    for (int t = t0; t < t1; t++) {
        u64 a0, a1 = 0;
        asm("mov.b64 %0, {%1,%2};" : "=l"(a0) : "f"(bj), "f"(0.0f));
        #pragma unroll
        for (int k = 0; k < 32; k++) {
            ulonglong2 v = h16[k];
            a0 = fma2p(a0, v.x, w[2*k]);
            a1 = fma2p(a1, v.y, w[2*k+1]);
        }
        float acc;
        {
            float xl, xh, yl, yh;
            asm("mov.b64 {%0,%1}, %2;" : "=f"(xl), "=f"(xh) : "l"(a0));
            asm("mov.b64 {%0,%1}, %2;" : "=f"(yl), "=f"(yh) : "l"(a1));
            acc = (xl + xh) + (yl + yh);
        }

        float r = 0.0f;
        if (j >= 128) {
            s_gh[j - 128] = acc + ((j < 256) ? gOwn : 0.0f);
        } else {
            r = fsig(acc + gOwn);
        }
        __syncthreads();

        if (isGate) {
            const float z = fsig(s_gh[e]);
            const float n = ftanh(gN + r * s_gh[e + 128]);
            hreg = n + z * (hreg - n);
            s_h[e] = hreg;
            if (layer == 0) g_h0[((size_t)t * BB + b) * HH + e] = hreg;
        }
        __syncthreads();

        if (t + 1 < t1) {
            const size_t off = (size_t)(t + 1) * S;
            if (j < 256) gOwn = pOwn[off] + biOwn;
            if (isGate)  gN   = pN[off] + biN;
        }
    }

    if (isGate) {
        if (layer == 1) g_hst1[b * HH + e] = hreg;
        if (c == NC - 1) hout[(size_t)b * HH + e] = hreg;
    }
}

// ---------------- launch ----------------------------------------------------
extern "C" void kernel_launch(void* const* d_in, const int* in_sizes, int n_in,
                              void* d_out, int out_size)
{
    const float* x     = (const float*)d_in[0];
    const float* W_ih0 = (const float*)d_in[1];
    const float* W_hh0 = (const float*)d_in[2];
    const float* b_ih0 = (const float*)d_in[3];
    const float* b_hh0 = (const float*)d_in[4];
    const float* W_ih1 = (const float*)d_in[5];
    const float* W_hh1 = (const float*)d_in[6];
    const float* b_ih1 = (const float*)d_in[7];
    const float* b_hh1 = (const float*)d_in[8];
    float* out = (float*)d_out;   // [L=2, B, H]

    static bool inited = false;
    static cudaStream_t sA, sB, sC;
    static cudaEvent_t evFork, evInit, evG0[NC], evR0[NC], evG1[NC];
    static __nv_bfloat16 *p_wh0, *p_wl0, *p_wh1, *p_wl1, *p_axh, *p_axl, *p_ahh, *p_ahl;
    static float *p_gi0, *p_gi1;
    if (!inited) {
        cudaStreamCreateWithFlags(&sA, cudaStreamNonBlocking);
        cudaStreamCreateWithFlags(&sB, cudaStreamNonBlocking);
        cudaStreamCreateWithFlags(&sC, cudaStreamNonBlocking);
        cudaEventCreateWithFlags(&evFork, cudaEventDisableTiming);
        cudaEventCreateWithFlags(&evInit, cudaEventDisableTiming);
        for (int i = 0; i < NC; i++) {
            cudaEventCreateWithFlags(&evG0[i], cudaEventDisableTiming);
            cudaEventCreateWithFlags(&evR0[i], cudaEventDisableTiming);
            cudaEventCreateWithFlags(&evG1[i], cudaEventDisableTiming);
        }
        void* p;
        cudaGetSymbolAddress(&p, g_wh);  p_wh0 = (__nv_bfloat16*)p; p_wh1 = p_wh0 + 384 * 128;
        cudaGetSymbolAddress(&p, g_wl);  p_wl0 = (__nv_bfloat16*)p; p_wl1 = p_wl0 + 384 * 128;
        cudaGetSymbolAddress(&p, g_axh); p_axh = (__nv_bfloat16*)p;
        cudaGetSymbolAddress(&p, g_axl); p_axl = (__nv_bfloat16*)p;
        cudaGetSymbolAddress(&p, g_ahh); p_ahh = (__nv_bfloat16*)p;
        cudaGetSymbolAddress(&p, g_ahl); p_ahl = (__nv_bfloat16*)p;
        cudaGetSymbolAddress(&p, g_gi0); p_gi0 = (float*)p;
        cudaGetSymbolAddress(&p, g_gi1); p_gi1 = (float*)p;
        inited = true;
    }

    cudaEventRecord(evFork, 0);
    cudaStreamWaitEvent(sA, evFork, 0);
    cudaStreamWaitEvent(sB, evFork, 0);
    cudaStreamWaitEvent(sC, evFork, 0);

    conv_w<<<(2 * 384 * 64 + 255) / 256, 256, 0, sA>>>(W_ih0, W_ih1);
    conv_x<<<(TT * 64 * 64) / 256, 256, 0, sA>>>(x);
    cudaEventRecord(evInit, sA);
    cudaStreamWaitEvent(sC, evInit, 0);   // gemm1 needs W1 images

    for (int c = 0; c < NC; c++) {
        gemm_wmma<<<64, 256, 0, sA>>>(p_axh, p_axl, p_wh0, p_wl0, p_gi0, c, 64);
        cudaEventRecord(evG0[c], sA);
    }
    for (int c = 0; c < NC; c++) {
        cudaStreamWaitEvent(sB, evG0[c], 0);
        rec_chunk<<<64, 384, 0, sB>>>(W_hh0, b_hh0, b_ih0, /*layer=*/0, c, out);
        cudaEventRecord(evR0[c], sB);
    }
    for (int c = 0; c < NC; c++) {
        cudaStreamWaitEvent(sC, evR0[c], 0);
        conv_h<<<(CC * 64 * 64) / 256, 256, 0, sC>>>(c);
        gemm_wmma<<<48, 256, 0, sC>>>(p_ahh, p_ahl, p_wh1, p_wl1, p_gi1, c, 48);
        cudaEventRecord(evG1[c], sC);
    }
    for (int c = 0; c < NC; c++) {
        cudaStreamWaitEvent(0, evG1[c], 0);
        rec_chunk<<<64, 384, 0, 0>>>(W_hh1, b_hh1, b_ih1, /*layer=*/1, c, out + BB * HH);
    }
}

// round 12
// speedup vs baseline: 1.0248x; 1.0248x over previous
#include <cuda_runtime.h>
#include <cuda_bf16.h>
#include <mma.h>
#include <cstdint>

using namespace nvcuda;

#define BB 64
#define TT 4096
#define DD 128
#define HH 128
#define GG 384            // 3*H, gates [r, z, n]

#define NC 16             // chunks
#define CC 256            // timesteps per chunk
#define APAD 136          // padded act row (elems) for conflict-free LDSM

typedef unsigned long long u64;
typedef unsigned int u32;

// ---------------- scratch (device globals; no allocation) -------------------
__device__ float g_gi0[(size_t)TT * BB * GG];   // raw gi (NO b_ih; rec adds it)
__device__ float g_gi1[(size_t)TT * BB * GG];
__device__ float g_h0 [(size_t)TT * BB * HH];
__device__ float g_hst1[BB * HH];
// bf16 hi/lo W images, row-major [384][128] per layer
__device__ __nv_bfloat16 g_wh[2][384 * 128];
__device__ __nv_bfloat16 g_wl[2][384 * 128];

// ---------------- helpers ---------------------------------------------------
__device__ __forceinline__ u64 fma2p(u64 d, u64 a, u64 b) {
    asm("fma.rn.f32x2 %0, %1, %2, %0;" : "+l"(d) : "l"(a), "l"(b)); return d;
}
__device__ __forceinline__ float fsig(float x) {
    return __fdividef(1.0f, 1.0f + __expf(-x));
}
__device__ __forceinline__ float ftanh(float x) {
    return 1.0f - __fdividef(2.0f, __expf(2.0f * x) + 1.0f);
}
__device__ __forceinline__ void split_pack(float x0, float x1, u32& hi, u32& lo) {
    __nv_bfloat16 h0 = __float2bfloat16(x0);
    __nv_bfloat16 h1 = __float2bfloat16(x1);
    __nv_bfloat16 l0 = __float2bfloat16(x0 - __bfloat162float(h0));
    __nv_bfloat16 l1 = __float2bfloat16(x1 - __bfloat162float(h1));
    hi = (u32)__bfloat16_as_ushort(h0) | ((u32)__bfloat16_as_ushort(h1) << 16);
    lo = (u32)__bfloat16_as_ushort(l0) | ((u32)__bfloat16_as_ushort(l1) << 16);
}

// ---------------- conversion: W -> bf16 hi/lo images ------------------------
__global__ void conv_w(const float* __restrict__ W0, const float* __restrict__ W1) {
    int i = blockIdx.x * blockDim.x + threadIdx.x;
    if (i >= 2 * 384 * 64) return;
    const int L = i / (384 * 64);
    const int rem = i % (384 * 64);
    const int j = rem >> 6;
    const int p = rem & 63;
    const float* W = L ? W1 : W0;
    u32 hi, lo;
    split_pack(W[(size_t)j * 128 + 2 * p], W[(size_t)j * 128 + 2 * p + 1], hi, lo);
    *(u32*)&g_wh[L][j * 128 + 2 * p] = hi;
    *(u32*)&g_wl[L][j * 128 + 2 * p] = lo;
}

// ---------------- WMMA GEMM -------------------------------------------------
// D[t][b][mtile*128 + j] = sum_k W[j,k] * act[b,k]  (3-term bf16 split, fp32 acc)
// CTA: 8 warps, one mtile (128 j-rows); warp owns 16 rows with W hi/lo
// fragments preloaded in REGISTERS (reused every t). Act is staged to smem
// with inline fp32->bf16 hi/lo split (padded rows, conflict-free LDSM).
__global__ void __launch_bounds__(256, 1) gemm_wmma(
    const float* __restrict__ act,
    int actMode,                     // 0: x layout [b][TT][128]; 1: h0 layout [t][b][128]
    const __nv_bfloat16* __restrict__ wh, const __nv_bfloat16* __restrict__ wl,
    float* __restrict__ dst, int t0, int t1, int nstripes)
{
    __shared__ __align__(16) __nv_bfloat16 s_ah[64 * APAD];
    __shared__ __align__(16) __nv_bfloat16 s_al[64 * APAD];
    const int tid = threadIdx.x;
    const int warp = tid >> 5;
    const int mtile = blockIdx.x / nstripes;
    const int stripe = blockIdx.x % nstripes;
    const int j0 = mtile * 128 + warp * 16;

    // preload this warp's W fragments (16 rows x 128 k), hi and lo
    wmma::fragment<wmma::matrix_a, 16, 16, 16, __nv_bfloat16, wmma::row_major> wf_h[8], wf_l[8];
    #pragma unroll
    for (int k = 0; k < 8; k++) {
        wmma::load_matrix_sync(wf_h[k], wh + (size_t)j0 * 128 + k * 16, 128);
        wmma::load_matrix_sync(wf_l[k], wl + (size_t)j0 * 128 + k * 16, 128);
    }

    for (int t = t0 + stripe; t < t1; t += nstripes) {
        // stage act (64 rows x 128 k) with inline hi/lo split
        for (int i = tid; i < 64 * 32; i += 256) {       // units of 4 floats
            const int b = i >> 5;
            const int kq = (i & 31) * 4;
            const float* src = (actMode == 0)
                ? act + ((size_t)b * TT + t) * DD + kq
                : act + ((size_t)t * BB + b) * HH + kq;
            float4 v = *(const float4*)src;
            u32 h0, l0, h1, l1;
            split_pack(v.x, v.y, h0, l0);
            split_pack(v.z, v.w, h1, l1);
            *(u32*)&s_ah[b * APAD + kq]     = h0;
            *(u32*)&s_ah[b * APAD + kq + 2] = h1;
            *(u32*)&s_al[b * APAD + kq]     = l0;
            *(u32*)&s_al[b * APAD + kq + 2] = l1;
        }
        __syncthreads();

        wmma::fragment<wmma::accumulator, 16, 16, 16, float> acc[4];
        #pragma unroll
        for (int n = 0; n < 4; n++) wmma::fill_fragment(acc[n], 0.0f);

        #pragma unroll
        for (int k = 0; k < 8; k++) {
            #pragma unroll
            for (int n = 0; n < 4; n++) {
                wmma::fragment<wmma::matrix_b, 16, 16, 16, __nv_bfloat16, wmma::col_major> bh, bl;
                wmma::load_matrix_sync(bh, s_ah + n * 16 * APAD + k * 16, APAD);
                wmma::load_matrix_sync(bl, s_al + n * 16 * APAD + k * 16, APAD);
                wmma::mma_sync(acc[n], wf_h[k], bh, acc[n]);   // xh*wh
                wmma::mma_sync(acc[n], wf_h[k], bl, acc[n]);   // xl*wh
                wmma::mma_sync(acc[n], wf_l[k], bh, acc[n]);   // xh*wl
            }
        }

        float* dp = dst + (size_t)t * BB * GG + j0;
        #pragma unroll
        for (int n = 0; n < 4; n++)
            wmma::store_matrix_sync(dp + (size_t)(n * 16) * GG, acc[n],
                                    GG, wmma::mem_col_major);
        __syncthreads();
    }
}

// ---------------- rec chunk (R9/R11 winner, b_ih folded) ---------------------
__global__ __launch_bounds__(384, 1) void rec_chunk(
    const float* __restrict__ Whh,
    const float* __restrict__ bhh,
    const float* __restrict__ bih,
    int layer, int c,
    float* __restrict__ hout)
{
    const int j = threadIdx.x;
    const int e = j & 127;
    const bool isGate = (j < 128);
    const int b = blockIdx.x;

    u64 w[64];
    {
        const ulonglong2* wr = (const ulonglong2*)(Whh + (size_t)j * 128);
        #pragma unroll
        for (int k = 0; k < 32; k++) { ulonglong2 v = wr[k]; w[2*k] = v.x; w[2*k+1] = v.y; }
    }
    const float bj = bhh[j];
    const float biOwn = (j < 256) ? bih[j] : 0.0f;
    const float biN   = isGate ? bih[256 + e] : 0.0f;

    const float* gi = layer ? g_gi1 : g_gi0;
    const size_t S = (size_t)BB * GG;
    const float* pOwn = gi + (size_t)b * GG + j;
    const float* pN   = gi + (size_t)b * GG + 256 + e;

    __shared__ __align__(16) float s_h[128];
    __shared__ float s_gh[256];

    const int t0 = c * CC, t1 = t0 + CC;

    float hreg = 0.0f;
    if (isGate) {
        if (c == 0) hreg = 0.0f;
        else if (layer == 0) hreg = g_h0[((size_t)(t0 - 1) * BB + b) * HH + e];
        else hreg = g_hst1[b * HH + e];
        s_h[e] = hreg;
    }
    __syncthreads();

    float gOwn = (j < 256) ? (pOwn[(size_t)t0 * S] + biOwn) : 0.0f;
    float gN   = isGate ? (pN[(size_t)t0 * S] + biN) : 0.0f;

    const ulonglong2* h16 = (const ulonglong2*)s_h;

    for (int t = t0; t < t1; t++) {
        u64 a0, a1 = 0;
        asm("mov.b64 %0, {%1,%2};" : "=l"(a0) : "f"(bj), "f"(0.0f));
        #pragma unroll
        for (int k = 0; k < 32; k++) {
            ulonglong2 v = h16[k];
            a0 = fma2p(a0, v.x, w[2*k]);
            a1 = fma2p(a1, v.y, w[2*k+1]);
        }
        float acc;
        {
            float xl, xh, yl, yh;
            asm("mov.b64 {%0,%1}, %2;" : "=f"(xl), "=f"(xh) : "l"(a0));
            asm("mov.b64 {%0,%1}, %2;" : "=f"(yl), "=f"(yh) : "l"(a1));
            acc = (xl + xh) + (yl + yh);
        }

        float r = 0.0f;
        if (j >= 128) {
            s_gh[j - 128] = acc + ((j < 256) ? gOwn : 0.0f);
        } else {
            r = fsig(acc + gOwn);
        }
        __syncthreads();

        if (isGate) {
            const float z = fsig(s_gh[e]);
            const float n = ftanh(gN + r * s_gh[e + 128]);
            hreg = n + z * (hreg - n);
            s_h[e] = hreg;
            if (layer == 0) g_h0[((size_t)t * BB + b) * HH + e] = hreg;
        }
        __syncthreads();

        if (t + 1 < t1) {
            const size_t off = (size_t)(t + 1) * S;
            if (j < 256) gOwn = pOwn[off] + biOwn;
            if (isGate)  gN   = pN[off] + biN;
        }
    }

    if (isGate) {
        if (layer == 1) g_hst1[b * HH + e] = hreg;
        if (c == NC - 1) hout[(size_t)b * HH + e] = hreg;
    }
}

// ---------------- launch ----------------------------------------------------
extern "C" void kernel_launch(void* const* d_in, const int* in_sizes, int n_in,
                              void* d_out, int out_size)
{
    const float* x     = (const float*)d_in[0];
    const float* W_ih0 = (const float*)d_in[1];
    const float* W_hh0 = (const float*)d_in[2];
    const float* b_ih0 = (const float*)d_in[3];
    const float* b_hh0 = (const float*)d_in[4];
    const float* W_ih1 = (const float*)d_in[5];
    const float* W_hh1 = (const float*)d_in[6];
    const float* b_ih1 = (const float*)d_in[7];
    const float* b_hh1 = (const float*)d_in[8];
    float* out = (float*)d_out;   // [L=2, B, H]

    static bool inited = false;
    static cudaStream_t sB, sC;
    static cudaEvent_t evFork, evG0, evR0[NC], evG1[NC];
    static __nv_bfloat16 *p_wh0, *p_wl0, *p_wh1, *p_wl1;
    static float *p_gi0, *p_gi1, *p_h0;
    if (!inited) {
        cudaStreamCreateWithFlags(&sB, cudaStreamNonBlocking);
        cudaStreamCreateWithFlags(&sC, cudaStreamNonBlocking);
        cudaEventCreateWithFlags(&evFork, cudaEventDisableTiming);
        cudaEventCreateWithFlags(&evG0, cudaEventDisableTiming);
        for (int i = 0; i < NC; i++) {
            cudaEventCreateWithFlags(&evR0[i], cudaEventDisableTiming);
            cudaEventCreateWithFlags(&evG1[i], cudaEventDisableTiming);
        }
        void* p;
        cudaGetSymbolAddress(&p, g_wh);  p_wh0 = (__nv_bfloat16*)p; p_wh1 = p_wh0 + 384 * 128;
        cudaGetSymbolAddress(&p, g_wl);  p_wl0 = (__nv_bfloat16*)p; p_wl1 = p_wl0 + 384 * 128;
        cudaGetSymbolAddress(&p, g_gi0); p_gi0 = (float*)p;
        cudaGetSymbolAddress(&p, g_gi1); p_gi1 = (float*)p;
        cudaGetSymbolAddress(&p, g_h0);  p_h0  = (float*)p;
        inited = true;
    }

    // Fork worker streams off the origin stream.
    cudaEventRecord(evFork, 0);
    cudaStreamWaitEvent(sB, evFork, 0);
    cudaStreamWaitEvent(sC, evFork, 0);

    // Up-front: W conversion + ALL of gi0 (144 CTAs, ~130us, then gone).
    conv_w<<<(2 * 384 * 64 + 255) / 256, 256, 0, sB>>>(W_ih0, W_ih1);
    gemm_wmma<<<3 * 48, 256, 0, sB>>>(x, /*actMode=*/0, p_wh0, p_wl0,
                                      p_gi0, 0, TT, 48);
    cudaEventRecord(evG0, sB);
    cudaStreamWaitEvent(sC, evG0, 0);     // gemm1 needs W1 images too

    // rec0 chain on sB (serial after gemm0).
    for (int c = 0; c < NC; c++) {
        rec_chunk<<<64, 384, 0, sB>>>(W_hh0, b_hh0, b_ih0, /*layer=*/0, c, out);
        cudaEventRecord(evR0[c], sB);
    }
    // gemm1 per chunk on sC (12 CTAs — fits in free SMs).
    for (int c = 0; c < NC; c++) {
        cudaStreamWaitEvent(sC, evR0[c], 0);
        gemm_wmma<<<3 * 4, 256, 0, sC>>>(p_h0, /*actMode=*/1, p_wh1, p_wl1,
                                         p_gi1, c * CC, (c + 1) * CC, 4);
        cudaEventRecord(evG1[c], sC);
    }
    // rec1 chain on origin stream (natural join).
    for (int c = 0; c < NC; c++) {
        cudaStreamWaitEvent(0, evG1[c], 0);
        rec_chunk<<<64, 384, 0, 0>>>(W_hh1, b_hh1, b_ih1, /*layer=*/1, c, out + BB * HH);
    }
}